// round 2
// baseline (speedup 1.0000x reference)
#include <cuda_runtime.h>
#include <math.h>

// Problem constants (fixed shapes from reference setup_inputs)
#define NB   8
#define ND   768
#define NCH  3
#define NMIX 5
#define NH   10
#define NS   10

#define PI2f      6.2831853071795864769f
#define ZITTERf   1e-4f
#define GEPSf     1e-20f

#define JSPLIT 6          // kernel1 j-splits (768 / 6 = 128)
#define JCHUNK (ND / JSPLIT)

// Scratch (device globals: allocation is forbidden)
__device__ float g_featp[JSPLIT][NB * ND * NCH * NMIX];   // partial feature sums
__device__ float g_w[NB * NCH * NMIX];                    // mixture weights

// ---------------------------------------------------------------------------
// Kernel 1: feature partials. feat[b,i,c,m] = sum_j K_m(x_i - x_j) * y_j
// grid (3 i-tiles, JSPLIT, NB*NCH), block 256 (one i per thread)
// ---------------------------------------------------------------------------
__global__ __launch_bounds__(256) void k1_feature(
    const float* __restrict__ xc, const float* __restrict__ yc,
    const float* __restrict__ mu, const float* __restrict__ inv_std)
{
    const int it = blockIdx.x;
    const int js = blockIdx.y;
    const int bc = blockIdx.z;
    const int b = bc / NCH, c = bc % NCH;
    const int i = it * 256 + threadIdx.x;

    float nA[NMIX], wm[NMIX];
#pragma unroll
    for (int m = 0; m < NMIX; ++m) {
        float s = __ldg(&inv_std[m]);
        nA[m] = -0.5f * PI2f * PI2f * s * s;
        wm[m] = PI2f * __ldg(&mu[m]);
    }

    const float xi = __ldg(&xc[(b * ND + i) * NCH + c]);
    float acc[NMIX] = {0.f, 0.f, 0.f, 0.f, 0.f};

    const int j0 = js * JCHUNK;
#pragma unroll 4
    for (int j = j0; j < j0 + JCHUNK; ++j) {
        float xj = __ldg(&xc[(b * ND + j) * NCH + c]);
        float yj = __ldg(&yc[(b * ND + j) * NCH + c]);
        float d = xi - xj;
        float d2 = d * d;
#pragma unroll
        for (int m = 0; m < NMIX; ++m) {
            float e  = __expf(nA[m] * d2);
            float cs = __cosf(wm[m] * d);
            acc[m] = fmaf(e * cs, yj, acc[m]);
        }
    }

    float* dst = &g_featp[js][((b * ND + i) * NCH + c) * NMIX];
#pragma unroll
    for (int m = 0; m < NMIX; ++m) dst[m] = acc[m];
}

// ---------------------------------------------------------------------------
// Kernel 2: MLP + Gumbel-softmax -> w[b,c,m]. grid NB, block 256.
// ---------------------------------------------------------------------------
__global__ __launch_bounds__(256) void k2_mlp_gumbel(
    const float* __restrict__ yc, const float* __restrict__ unif,
    const float* __restrict__ W1, const float* __restrict__ b1,
    const float* __restrict__ W2, const float* __restrict__ b2,
    const float* __restrict__ W3, const float* __restrict__ b3,
    const float* __restrict__ W4, const float* __restrict__ b4,
    const float* __restrict__ W5, const float* __restrict__ b5)
{
    const int b = blockIdx.x;
    const int tid = threadIdx.x;
    const int lane = tid & 31;

    __shared__ float spsum[NCH * NH];      // 30
    __shared__ float sflat[NCH * NH];
    __shared__ float sh2[NH], sh3[NH], sh4[NH];
    __shared__ float sll[NCH * NMIX];      // 15
    __shared__ float swacc[NCH * NMIX];

    if (tid < NCH * NH) spsum[tid] = 0.f;
    if (tid < NCH * NMIX) swacc[tid] = 0.f;
    __syncthreads();

    // Stage A: hsum[c*10+k] += relu(tif @ W1.T + b1), rows (i,c)
    float hsum[NCH * NH];
#pragma unroll
    for (int t = 0; t < NCH * NH; ++t) hsum[t] = 0.f;

    for (int i = tid; i < ND; i += 256) {
#pragma unroll
        for (int c = 0; c < NCH; ++c) {
            float fs[NMIX];
#pragma unroll
            for (int m = 0; m < NMIX; ++m) {
                float s = 0.f;
#pragma unroll
                for (int js = 0; js < JSPLIT; ++js)
                    s += g_featp[js][((b * ND + i) * NCH + c) * NMIX + m];
                fs[m] = s;
            }
            float y = __ldg(&yc[(b * ND + i) * NCH + c]);
#pragma unroll
            for (int m = 0; m < NMIX; ++m) fs[m] += ZITTERf * y;
#pragma unroll
            for (int k = 0; k < NH; ++k) {
                float t = __ldg(&b1[k]);
#pragma unroll
                for (int m = 0; m < NMIX; ++m)
                    t = fmaf(fs[m], __ldg(&W1[k * (NMIX + 1) + m]), t);
                t = fmaf(y, __ldg(&W1[k * (NMIX + 1) + NMIX]), t);
                hsum[c * NH + k] += fmaxf(t, 0.f);
            }
        }
    }
    // block reduce via warp shuffles + shared atomics
#pragma unroll
    for (int t = 0; t < NCH * NH; ++t) {
        float v = hsum[t];
#pragma unroll
        for (int o = 16; o > 0; o >>= 1) v += __shfl_down_sync(0xffffffffu, v, o);
        if (lane == 0) atomicAdd(&spsum[t], v);
    }
    __syncthreads();
    if (tid < NCH * NH) sflat[tid] = spsum[tid] * (1.0f / (float)ND);
    __syncthreads();

    // MLP chain (tiny)
    if (tid < NH) {
        float a = __ldg(&b2[tid]);
        for (int t = 0; t < NCH * NH; ++t) a = fmaf(sflat[t], __ldg(&W2[tid * NCH * NH + t]), a);
        sh2[tid] = fmaxf(a, 0.f);
    }
    __syncthreads();
    if (tid < NH) {
        float a = __ldg(&b3[tid]);
        for (int t = 0; t < NH; ++t) a = fmaf(sh2[t], __ldg(&W3[tid * NH + t]), a);
        sh3[tid] = fmaxf(a, 0.f);
    }
    __syncthreads();
    if (tid < NH) {
        float a = __ldg(&b4[tid]);
        for (int t = 0; t < NH; ++t) a = fmaf(sh3[t], __ldg(&W4[tid * NH + t]), a);
        sh4[tid] = fmaxf(a, 0.f);
    }
    __syncthreads();
    if (tid < NCH * NMIX) {
        float a = __ldg(&b5[tid]);
        for (int k = 0; k < NH; ++k) a = fmaf(sh4[k], __ldg(&W5[tid * NH + k]), a);
        sll[tid] = a;
    }
    __syncthreads();

    // Gumbel-softmax, one thread per (s, c)
    if (tid < NS * NCH) {
        int s = tid / NCH, c = tid % NCH;
        float z[NMIX], zm = -1e30f;
#pragma unroll
        for (int m = 0; m < NMIX; ++m) {
            float u = __ldg(&unif[((b * NS + s) * NCH + c) * NMIX + m]);
            float g = -__logf(-__logf(u + GEPSf));
            z[m] = (g + sll[c * NMIX + m]) * 10.0f;   // /TEMP, TEMP=0.1
            zm = fmaxf(zm, z[m]);
        }
        float e[NMIX], sum = 0.f;
#pragma unroll
        for (int m = 0; m < NMIX; ++m) { e[m] = __expf(z[m] - zm); sum += e[m]; }
        float inv = 1.0f / (sum * (float)NS);         // fold mean over ns
#pragma unroll
        for (int m = 0; m < NMIX; ++m)
            atomicAdd(&swacc[c * NMIX + m], e[m] * inv);
    }
    __syncthreads();
    if (tid < NCH * NMIX) g_w[b * NCH * NMIX + tid] = swacc[tid];
}

// ---------------------------------------------------------------------------
// Kernel 3: out[b,i,j,c] = sum_m w[b,c,m] * K_m(d) + (i==j) diag[c]
// Symmetric: only upper 32x32 tiles, mirror via padded shared transpose.
// grid (24, 24, NB), block (32, 8). Early-exit lower tiles.
// ---------------------------------------------------------------------------
#define TPAD 99   // 32*3 = 96 padded to 99 -> stride 3 mod 32 (conflict-free)

__global__ __launch_bounds__(256) void k3_weighted(
    const float* __restrict__ xc, const float* __restrict__ mu,
    const float* __restrict__ inv_std, const float* __restrict__ likerr,
    float* __restrict__ out)
{
    const int bx = blockIdx.x;          // i tile
    const int by = blockIdx.y;          // j tile
    if (by < bx) return;                // symmetry
    const int b = blockIdx.z;
    const int i0 = bx * 32, j0 = by * 32;
    const int tx = threadIdx.x, ty = threadIdx.y;
    const int tid = ty * 32 + tx;

    __shared__ float sxi[32 * NCH], sxj[32 * NCH];
    __shared__ float swv[NCH * NMIX], snA[NMIX], swm[NMIX], sdiag[NCH];
    __shared__ float tile[32][TPAD];

    if (tid < 96)       sxi[tid]      = xc[(b * ND + i0 + tid / 3) * NCH + tid % 3];
    else if (tid < 192) sxj[tid - 96] = xc[(b * ND + j0 + (tid - 96) / 3) * NCH + (tid - 96) % 3];
    if (tid < NCH * NMIX) swv[tid] = g_w[b * NCH * NMIX + tid];
    if (tid < NMIX) {
        float s = inv_std[tid];
        snA[tid] = -0.5f * PI2f * PI2f * s * s;
        swm[tid] = PI2f * mu[tid];
    }
    if (tid < NCH) {
        float l = fminf(fmaxf(likerr[tid], 0.1f), 1.0f);
        sdiag[tid] = ZITTERf + l * l;
    }
    __syncthreads();

#pragma unroll
    for (int r = 0; r < 4; ++r) {
        int ti = ty + 8 * r;
        int i = i0 + ti;
        int j = j0 + tx;
        int base = ((b * ND + i) * ND + j) * NCH;
#pragma unroll
        for (int c = 0; c < NCH; ++c) {
            float d  = sxi[ti * NCH + c] - sxj[tx * NCH + c];
            float d2 = d * d;
            float acc = 0.f;
#pragma unroll
            for (int m = 0; m < NMIX; ++m) {
                float e  = __expf(snA[m] * d2);
                float cs = __cosf(swm[m] * d);
                acc = fmaf(swv[c * NMIX + m], e * cs, acc);
            }
            if (i == j) acc += sdiag[c];
            out[base + c] = acc;
            tile[ti][tx * NCH + c] = acc;
        }
    }

    if (bx != by) {
        __syncthreads();
#pragma unroll
        for (int r = 0; r < 4; ++r) {
            int jj = ty + 8 * r;
            int base = ((b * ND + j0 + jj) * ND + (i0 + tx)) * NCH;
#pragma unroll
            for (int c = 0; c < NCH; ++c)
                out[base + c] = tile[tx][jj * NCH + c];
        }
    }
}

// ---------------------------------------------------------------------------
// Launch. Input order: xc, yc, mu, inv_std, likerr, unif, W1..b5
// ---------------------------------------------------------------------------
extern "C" void kernel_launch(void* const* d_in, const int* in_sizes, int n_in,
                              void* d_out, int out_size)
{
    const float* xc      = (const float*)d_in[0];
    const float* yc      = (const float*)d_in[1];
    const float* mu      = (const float*)d_in[2];
    const float* inv_std = (const float*)d_in[3];
    const float* likerr  = (const float*)d_in[4];
    const float* unif    = (const float*)d_in[5];
    const float* W1 = (const float*)d_in[6];  const float* b1 = (const float*)d_in[7];
    const float* W2 = (const float*)d_in[8];  const float* b2 = (const float*)d_in[9];
    const float* W3 = (const float*)d_in[10]; const float* b3 = (const float*)d_in[11];
    const float* W4 = (const float*)d_in[12]; const float* b4 = (const float*)d_in[13];
    const float* W5 = (const float*)d_in[14]; const float* b5 = (const float*)d_in[15];
    float* out = (float*)d_out;

    dim3 g1(ND / 256, JSPLIT, NB * NCH);
    k1_feature<<<g1, 256>>>(xc, yc, mu, inv_std);

    k2_mlp_gumbel<<<NB, 256>>>(yc, unif, W1, b1, W2, b2, W3, b3, W4, b4, W5, b5);

    dim3 g3(ND / 32, ND / 32, NB);
    dim3 t3(32, 8);
    k3_weighted<<<g3, t3>>>(xc, mu, inv_std, likerr, out);
}

// round 3
// speedup vs baseline: 1.4050x; 1.4050x over previous
#include <cuda_runtime.h>
#include <math.h>

// Problem constants (fixed shapes from reference setup_inputs)
#define NB   8
#define ND   768
#define NCH  3
#define NMIX 5
#define NH   10
#define NS   10

#define PI2f      6.2831853071795864769f
#define ZITTERf   1e-4f
#define GEPSf     1e-20f

#define T_TILES  24          // ND/32
#define NGRP     6           // groups of 4 column-tiles
#define NPAIR    300         // 24*25/2 upper-tri tile pairs (k3)
#define NSLOT    30          // 24 j-slots + 6 group i-slots

// Scratch (device globals: allocation is forbidden)
__device__ float g_featp[NSLOT][NB * ND * NCH * NMIX];  // exclusive partial features
__device__ float g_hpart[NB][T_TILES][NCH * NH];        // k2a partial relu-sums
__device__ float g_w[NB * NCH * NMIX];                  // mixture weights

// ---------------------------------------------------------------------------
// Kernel 1 (symmetric): feat[b,i,c,m] = sum_j K_m(x_i-x_j) * y_j
// Strip block: row-tile ti (32 rows) x column-group g (4 tiles of 32).
// Processes tiles tj in group with tj >= ti; each K value computed once:
//   i-part: rows ti  += K * y_j   (register acc, slot 24+g)
//   j-part: rows tj  += K * y_i   (shared reduce, slot ti)   [skip if tj==ti]
// grid (24*6, NB*NCH), block (32,8).
// ---------------------------------------------------------------------------
__global__ __launch_bounds__(256) void k1_feature_sym(
    const float* __restrict__ xc, const float* __restrict__ yc,
    const float* __restrict__ mu, const float* __restrict__ inv_std)
{
    const int ti = blockIdx.x / NGRP;
    const int g  = blockIdx.x % NGRP;
    if (ti > 4 * g + 3) return;               // strip fully below diagonal
    const int bc = blockIdx.y;
    const int b = bc / NCH, c = bc % NCH;

    const int tx = threadIdx.x;               // lane = j within tile
    const int ty = threadIdx.y;               // warp id
    const int tid = ty * 32 + tx;

    __shared__ float sxi[32], syi[32];
    __shared__ float sxj[128], syj[128];
    __shared__ float sj[8][160];

    if (tid < 32) {
        sxi[tid] = xc[(b * ND + ti * 32 + tid) * NCH + c];
        syi[tid] = yc[(b * ND + ti * 32 + tid) * NCH + c];
    }
    {
        const int j0 = g * 128;
        if (tid < 128) {
            sxj[tid] = xc[(b * ND + j0 + tid) * NCH + c];
            syj[tid] = yc[(b * ND + j0 + tid) * NCH + c];
        }
    }
    __syncthreads();

    float nA[NMIX], wm[NMIX];
#pragma unroll
    for (int m = 0; m < NMIX; ++m) {
        float s = __ldg(&inv_std[m]);
        nA[m] = -0.5f * PI2f * PI2f * s * s;
        wm[m] = PI2f * __ldg(&mu[m]);
    }

    float xir[4], yir[4];
#pragma unroll
    for (int r = 0; r < 4; ++r) { xir[r] = sxi[ty + 8 * r]; yir[r] = syi[ty + 8 * r]; }

    float acc_i[4][NMIX];
#pragma unroll
    for (int r = 0; r < 4; ++r)
#pragma unroll
        for (int m = 0; m < NMIX; ++m) acc_i[r][m] = 0.f;

    for (int tjl = 0; tjl < 4; ++tjl) {
        const int tj = g * 4 + tjl;
        if (tj < ti) continue;                // uniform branch
        const float xjv = sxj[tjl * 32 + tx];
        const float yjv = syj[tjl * 32 + tx];
        float accjp[NMIX] = {0.f, 0.f, 0.f, 0.f, 0.f};

#pragma unroll
        for (int r = 0; r < 4; ++r) {
            float d  = xir[r] - xjv;
            float d2 = d * d;
#pragma unroll
            for (int m = 0; m < NMIX; ++m) {
                float e  = __expf(nA[m] * d2);
                float cs = __cosf(wm[m] * d);
                float kv = e * cs;
                acc_i[r][m] = fmaf(kv, yjv, acc_i[r][m]);
                accjp[m]    = fmaf(kv, yir[r], accjp[m]);
            }
        }

        if (tj != ti) {                       // j-part -> slot ti
#pragma unroll
            for (int m = 0; m < NMIX; ++m) sj[ty][tx * 5 + m] = accjp[m];
            __syncthreads();
            if (tid < 160) {
                float s = 0.f;
#pragma unroll
                for (int w = 0; w < 8; ++w) s += sj[w][tid];
                int jl = tid / 5, m = tid % 5;
                g_featp[ti][((b * ND + tj * 32 + jl) * NCH + c) * NMIX + m] = s;
            }
            __syncthreads();
        }
    }

    // i-part: lane reduce over j (32 lanes), lane 0 stores. slot 24+g
#pragma unroll
    for (int r = 0; r < 4; ++r) {
        int base = ((b * ND + ti * 32 + ty + 8 * r) * NCH + c) * NMIX;
#pragma unroll
        for (int m = 0; m < NMIX; ++m) {
            float v = acc_i[r][m];
            v += __shfl_down_sync(0xffffffffu, v, 16);
            v += __shfl_down_sync(0xffffffffu, v, 8);
            v += __shfl_down_sync(0xffffffffu, v, 4);
            v += __shfl_down_sync(0xffffffffu, v, 2);
            v += __shfl_down_sync(0xffffffffu, v, 1);
            if (tx == 0) g_featp[24 + g][base + m] = v;
        }
    }
}

// ---------------------------------------------------------------------------
// Kernel 2a: partial relu-hidden sums per 32-row tile.
// grid (24, NB), block 128 (96 active). Reads only populated slots:
// row-tile t: j-slots [0,t) and i-slots 24+[t/4, 6).
// ---------------------------------------------------------------------------
__global__ __launch_bounds__(128) void k2a_hidden(
    const float* __restrict__ yc,
    const float* __restrict__ W1, const float* __restrict__ b1)
{
    const int blk = blockIdx.x;               // row tile
    const int b   = blockIdx.y;
    const int t   = threadIdx.x;

    __shared__ float spart[96][NH];

    if (t < 96) {
        const int i = blk * 32 + t / 3;
        const int c = t % 3;
        const int base = ((b * ND + i) * NCH + c) * NMIX;

        float fs[NMIX] = {0.f, 0.f, 0.f, 0.f, 0.f};
        for (int s = 0; s < blk; ++s) {
#pragma unroll
            for (int m = 0; m < NMIX; ++m) fs[m] += g_featp[s][base + m];
        }
        for (int gg = blk >> 2; gg < NGRP; ++gg) {
#pragma unroll
            for (int m = 0; m < NMIX; ++m) fs[m] += g_featp[24 + gg][base + m];
        }
        const float y = __ldg(&yc[(b * ND + i) * NCH + c]);
#pragma unroll
        for (int m = 0; m < NMIX; ++m) fs[m] += ZITTERf * y;

#pragma unroll
        for (int k = 0; k < NH; ++k) {
            float h = __ldg(&b1[k]);
#pragma unroll
            for (int m = 0; m < NMIX; ++m)
                h = fmaf(fs[m], __ldg(&W1[k * (NMIX + 1) + m]), h);
            h = fmaf(y, __ldg(&W1[k * (NMIX + 1) + NMIX]), h);
            spart[t][k] = fmaxf(h, 0.f);
        }
    }
    __syncthreads();

    if (t < NCH * NH) {                       // t = c*10 + k
        const int c = t / NH, k = t % NH;
        float s = 0.f;
#pragma unroll
        for (int r = 0; r < 32; ++r) s += spart[r * 3 + c][k];
        g_hpart[b][blk][t] = s;
    }
}

// ---------------------------------------------------------------------------
// Kernel 2b: finish mean, MLP chain, Gumbel-softmax -> g_w. grid NB, block 32.
// ---------------------------------------------------------------------------
__global__ __launch_bounds__(32) void k2b_mlp_gumbel(
    const float* __restrict__ unif,
    const float* __restrict__ W2, const float* __restrict__ b2,
    const float* __restrict__ W3, const float* __restrict__ b3,
    const float* __restrict__ W4, const float* __restrict__ b4,
    const float* __restrict__ W5, const float* __restrict__ b5)
{
    const int b = blockIdx.x;
    const int tid = threadIdx.x;

    __shared__ float sflat[NCH * NH];
    __shared__ float sh2[NH], sh3[NH], sh4[NH];
    __shared__ float sll[NCH * NMIX];
    __shared__ float sg[NS * NCH][NMIX];

    if (tid < NCH * NH) {
        float s = 0.f;
        for (int p = 0; p < T_TILES; ++p) s += g_hpart[b][p][tid];
        sflat[tid] = s * (1.0f / (float)ND);
    }
    __syncthreads();
    if (tid < NH) {
        float a = __ldg(&b2[tid]);
        for (int t = 0; t < NCH * NH; ++t) a = fmaf(sflat[t], __ldg(&W2[tid * NCH * NH + t]), a);
        sh2[tid] = fmaxf(a, 0.f);
    }
    __syncthreads();
    if (tid < NH) {
        float a = __ldg(&b3[tid]);
        for (int t = 0; t < NH; ++t) a = fmaf(sh2[t], __ldg(&W3[tid * NH + t]), a);
        sh3[tid] = fmaxf(a, 0.f);
    }
    __syncthreads();
    if (tid < NH) {
        float a = __ldg(&b4[tid]);
        for (int t = 0; t < NH; ++t) a = fmaf(sh3[t], __ldg(&W4[tid * NH + t]), a);
        sh4[tid] = fmaxf(a, 0.f);
    }
    __syncthreads();
    if (tid < NCH * NMIX) {
        float a = __ldg(&b5[tid]);
        for (int k = 0; k < NH; ++k) a = fmaf(sh4[k], __ldg(&W5[tid * NH + k]), a);
        sll[tid] = a;
    }
    __syncthreads();

    if (tid < NS * NCH) {                     // tid = s*3 + c
        const int s = tid / NCH, c = tid % NCH;
        float z[NMIX], zm = -1e30f;
#pragma unroll
        for (int m = 0; m < NMIX; ++m) {
            float u = __ldg(&unif[((b * NS + s) * NCH + c) * NMIX + m]);
            float gb = -__logf(-__logf(u + GEPSf));
            z[m] = (gb + sll[c * NMIX + m]) * 10.0f;   // /TEMP, TEMP=0.1
            zm = fmaxf(zm, z[m]);
        }
        float e[NMIX], sum = 0.f;
#pragma unroll
        for (int m = 0; m < NMIX; ++m) { e[m] = __expf(z[m] - zm); sum += e[m]; }
        float inv = 1.0f / (sum * (float)NS);          // fold mean over ns
#pragma unroll
        for (int m = 0; m < NMIX; ++m) sg[tid][m] = e[m] * inv;
    }
    __syncthreads();
    if (tid < NCH * NMIX) {                   // tid = c*5 + m
        const int c = tid / NMIX, m = tid % NMIX;
        float w = 0.f;
#pragma unroll
        for (int s = 0; s < NS; ++s) w += sg[s * NCH + c][m];
        g_w[b * NCH * NMIX + tid] = w;
    }
}

// ---------------------------------------------------------------------------
// Kernel 3: out[b,i,j,c] = sum_m w[b,c,m] * K_m(d) + (i==j) diag[c]
// Upper-triangle pair decode, mirror via padded shared transpose.
// grid (300, NB), block (32, 8).
// ---------------------------------------------------------------------------
#define TPAD 99   // 32*3 padded -> stride 3 mod 32 conflict-free

__global__ __launch_bounds__(256) void k3_weighted(
    const float* __restrict__ xc, const float* __restrict__ mu,
    const float* __restrict__ inv_std, const float* __restrict__ likerr,
    float* __restrict__ out)
{
    // decode upper-tri pair (ti <= tj)
    int p = blockIdx.x;
    int ti = 0, rem = T_TILES;
    while (p >= rem) { p -= rem; ++ti; --rem; }
    const int tj = ti + p;

    const int b = blockIdx.y;
    const int i0 = ti * 32, j0 = tj * 32;
    const int tx = threadIdx.x, ty = threadIdx.y;
    const int tid = ty * 32 + tx;

    __shared__ float sxi[32 * NCH], sxj[32 * NCH];
    __shared__ float swv[NCH * NMIX], snA[NMIX], swm[NMIX], sdiag[NCH];
    __shared__ float tile[32][TPAD];

    if (tid < 96)       sxi[tid]      = xc[(b * ND + i0 + tid / 3) * NCH + tid % 3];
    else if (tid < 192) sxj[tid - 96] = xc[(b * ND + j0 + (tid - 96) / 3) * NCH + (tid - 96) % 3];
    if (tid < NCH * NMIX) swv[tid] = g_w[b * NCH * NMIX + tid];
    if (tid < NMIX) {
        float s = inv_std[tid];
        snA[tid] = -0.5f * PI2f * PI2f * s * s;
        swm[tid] = PI2f * mu[tid];
    }
    if (tid < NCH) {
        float l = fminf(fmaxf(likerr[tid], 0.1f), 1.0f);
        sdiag[tid] = ZITTERf + l * l;
    }
    __syncthreads();

#pragma unroll
    for (int r = 0; r < 4; ++r) {
        int tr = ty + 8 * r;
        int i = i0 + tr;
        int j = j0 + tx;
        int base = ((b * ND + i) * ND + j) * NCH;
#pragma unroll
        for (int c = 0; c < NCH; ++c) {
            float d  = sxi[tr * NCH + c] - sxj[tx * NCH + c];
            float d2 = d * d;
            float acc = 0.f;
#pragma unroll
            for (int m = 0; m < NMIX; ++m) {
                float e  = __expf(snA[m] * d2);
                float cs = __cosf(swm[m] * d);
                acc = fmaf(swv[c * NMIX + m], e * cs, acc);
            }
            if (i == j) acc += sdiag[c];
            out[base + c] = acc;
            tile[tr][tx * NCH + c] = acc;
        }
    }

    if (ti != tj) {
        __syncthreads();
#pragma unroll
        for (int r = 0; r < 4; ++r) {
            int jj = ty + 8 * r;
            int base = ((b * ND + j0 + jj) * ND + (i0 + tx)) * NCH;
#pragma unroll
            for (int c = 0; c < NCH; ++c)
                out[base + c] = tile[tx][jj * NCH + c];
        }
    }
}

// ---------------------------------------------------------------------------
// Launch. Input order: xc, yc, mu, inv_std, likerr, unif, W1..b5
// ---------------------------------------------------------------------------
extern "C" void kernel_launch(void* const* d_in, const int* in_sizes, int n_in,
                              void* d_out, int out_size)
{
    const float* xc      = (const float*)d_in[0];
    const float* yc      = (const float*)d_in[1];
    const float* mu      = (const float*)d_in[2];
    const float* inv_std = (const float*)d_in[3];
    const float* likerr  = (const float*)d_in[4];
    const float* unif    = (const float*)d_in[5];
    const float* W1 = (const float*)d_in[6];  const float* b1 = (const float*)d_in[7];
    const float* W2 = (const float*)d_in[8];  const float* b2 = (const float*)d_in[9];
    const float* W3 = (const float*)d_in[10]; const float* b3 = (const float*)d_in[11];
    const float* W4 = (const float*)d_in[12]; const float* b4 = (const float*)d_in[13];
    const float* W5 = (const float*)d_in[14]; const float* b5 = (const float*)d_in[15];
    float* out = (float*)d_out;

    dim3 g1(T_TILES * NGRP, NB * NCH);
    dim3 t1(32, 8);
    k1_feature_sym<<<g1, t1>>>(xc, yc, mu, inv_std);

    dim3 g2a(T_TILES, NB);
    k2a_hidden<<<g2a, 128>>>(yc, W1, b1);

    k2b_mlp_gumbel<<<NB, 32>>>(unif, W2, b2, W3, b3, W4, b4, W5, b5);

    dim3 g3(NPAIR, NB);
    dim3 t3(32, 8);
    k3_weighted<<<g3, t3>>>(xc, mu, inv_std, likerr, out);
}